// round 15
// baseline (speedup 1.0000x reference)
#include <cuda_runtime.h>

// ForwardKinematicsLayer: SMPL 24-joint FK, B=262144 bodies.
// Inputs: local_rots [B,24,3,3] f32, root_pos [B,3] f32, offsets [24,3] f32
// Output: concat( global_pos [B,24,3], global_rots [B,24,3,3] ) f32
//
// R14: persistent blocks + double-buffered cp.async prefetch on top of the
// R12 float4 pipeline (110 us, DRAM 57%). Next tile's stage-in is issued via
// cp.async BEFORE waiting on the current tile, so DRAM reads flow during
// compute and stage-out -> removes the phase-serialization that capped DRAM
// at 57%. 2 buffers x 56 KB -> 2 blocks/SM; cp.async provides MLP without
// warps. Grid = 2*148 persistent blocks, grid-stride over tiles.

#define NJ 24
#define NB 48                   // bodies per tile
#define NT 256                  // threads per block
#define SW 292                  // words per body row (73 f4; 73%8==1 -> conflict-free)
#define TILE_WORDS (NB * SW)    // 14016 floats = 56,064 B
#define SMEM_BYTES (2 * TILE_WORDS * 4)   // 112,128 B -> 2 blocks/SM
#define GRID_BLOCKS 296         // 2 * 148 SMs, persistent

extern __shared__ float sm[];

__device__ __forceinline__ unsigned su32(const void* p) {
    return (unsigned)__cvta_generic_to_shared(p);
}

__device__ __forceinline__ void stage_in_async(const float* __restrict__ lr,
                                               const float* __restrict__ root,
                                               float* __restrict__ buf,
                                               int b0, int nb, int t)
{
    const float4* src4 = reinterpret_cast<const float4*>(lr + (size_t)b0 * 216);
    float4* dst4 = reinterpret_cast<float4*>(buf);
    const int total = nb * 54;
    #pragma unroll 4
    for (int idx = t; idx < NB * 54; idx += NT) {       // 2592 f4
        if (idx < total) {
            int body = idx / 54;
            int q    = idx - body * 54;
            asm volatile("cp.async.cg.shared.global [%0], [%1], 16;\n"
                         :: "r"(su32(dst4 + body * 73 + q)), "l"(src4 + idx));
        }
    }
    const float* rsrc = root + (size_t)b0 * 3;
    if (t < NB * 3) {                                    // 144 x 4B
        int body = t / 3;
        int c    = t - body * 3;
        if (body < nb)
            asm volatile("cp.async.ca.shared.global [%0], [%1], 4;\n"
                         :: "r"(su32(buf + body * SW + 288 + c)), "l"(rsrc + t));
    }
}

__global__ __launch_bounds__(NT)
void fk_kernel(const float* __restrict__ lr,
               const float* __restrict__ root,
               const float* __restrict__ off,
               float* __restrict__ out,
               int B)
{
    const int t = threadIdx.x;
    const int numTiles = (B + NB - 1) / NB;
    const int stride = gridDim.x;

    int k = blockIdx.x;
    if (k >= numTiles) return;

    float* buf0 = sm;
    float* buf1 = sm + TILE_WORDS;

    // Prologue: stage first tile into buf0.
    stage_in_async(lr, root, buf0, k * NB, min(NB, B - k * NB), t);
    asm volatile("cp.async.commit_group;\n");

    int pb = 0;
    for (; k < numTiles; k += stride) {
        const int b0 = k * NB;
        const int nb = min(NB, B - b0);
        float* cur = pb ? buf1 : buf0;
        float* nxt = pb ? buf0 : buf1;

        // Prefetch next tile into the other buffer (flows during compute/drain).
        const int knext = k + stride;
        const bool have_next = (knext < numTiles);
        if (have_next)
            stage_in_async(lr, root, nxt, knext * NB, min(NB, B - knext * NB), t);
        asm volatile("cp.async.commit_group;\n");

        // Wait for CURRENT tile only (leave the newest group in flight).
        if (have_next)
            asm volatile("cp.async.wait_group 1;\n");
        else
            asm volatile("cp.async.wait_group 0;\n");
        __syncthreads();

        // ---------- compute: register FK chain, one thread per body ----------
        if (t < nb) {
            constexpr int PAR[NJ] = {-1, 0, 0, 0, 1, 2, 3, 4, 5, 6, 7, 8,
                                      9, 9, 9, 12, 13, 14, 16, 17, 18, 19, 20, 21};
            const float4* cur4 = reinterpret_cast<const float4*>(cur);
            const int tw = t * 73;
            float* smw = cur + t * SW;

            float gr[NJ][9];
            float gp[NJ][3];
            int rc = 0, pc = 0;
            float re0, re1, re2, re3, pe0, pe1, pe2, pe3;

#define ROT_PUSH(v) do {                                                    \
            const int _p = rc & 3;                                          \
            if (_p == 0) re0 = (v); else if (_p == 1) re1 = (v);            \
            else if (_p == 2) re2 = (v); else re3 = (v);                    \
            if (_p == 3)                                                    \
                *reinterpret_cast<float4*>(smw + (rc - 3)) =                \
                    make_float4(re0, re1, re2, re3);                        \
            rc++;                                                           \
        } while (0)

#define POS_PUSH(v) do {                                                    \
            const int _p = pc & 3;                                          \
            if (_p == 0) pe0 = (v); else if (_p == 1) pe1 = (v);            \
            else if (_p == 2) pe2 = (v); else pe3 = (v);                    \
            if (_p == 3)                                                    \
                *reinterpret_cast<float4*>(smw + 216 + (pc - 3)) =          \
                    make_float4(pe0, pe1, pe2, pe3);                        \
            pc++;                                                           \
        } while (0)

            #pragma unroll
            for (int j = 0; j < NJ; ++j) {
                const int q0 = (9 * j) / 4;
                const int r  = (9 * j) & 3;
                float4 w0 = cur4[tw + q0];
                float4 w1 = cur4[tw + q0 + 1];
                float4 w2 = cur4[tw + q0 + 2];
                float wv[12] = {w0.x, w0.y, w0.z, w0.w,
                                w1.x, w1.y, w1.z, w1.w,
                                w2.x, w2.y, w2.z, w2.w};
                float l[9];
                #pragma unroll
                for (int i = 0; i < 9; ++i) l[i] = wv[r + i];

                if (j == 0) {
                    #pragma unroll
                    for (int i = 0; i < 9; ++i) gr[0][i] = l[i];
                    #pragma unroll
                    for (int i = 0; i < 3; ++i) gp[0][i] = smw[288 + i];
                } else {
                    const int p = PAR[j];
                    const float o0 = __ldg(&off[j * 3 + 0]);
                    const float o1 = __ldg(&off[j * 3 + 1]);
                    const float o2 = __ldg(&off[j * 3 + 2]);
                    #pragma unroll
                    for (int i = 0; i < 3; ++i)
                        gp[j][i] = gp[p][i]
                                 + gr[p][i * 3 + 0] * o0
                                 + gr[p][i * 3 + 1] * o1
                                 + gr[p][i * 3 + 2] * o2;
                    #pragma unroll
                    for (int i = 0; i < 3; ++i) {
                        const float a0 = gr[p][i * 3 + 0];
                        const float a1 = gr[p][i * 3 + 1];
                        const float a2 = gr[p][i * 3 + 2];
                        #pragma unroll
                        for (int kk = 0; kk < 3; ++kk)
                            gr[j][i * 3 + kk] = a0 * l[0 + kk] + a1 * l[3 + kk] + a2 * l[6 + kk];
                    }
                }
                #pragma unroll
                for (int i = 0; i < 9; ++i) ROT_PUSH(gr[j][i]);
                #pragma unroll
                for (int i = 0; i < 3; ++i) POS_PUSH(gp[j][i]);
            }
#undef ROT_PUSH
#undef POS_PUSH
        }
        __syncthreads();

        // ---------- stage-out tile k ----------
        {
            const float4* cur4 = reinterpret_cast<const float4*>(cur);
            float4* pd4 = reinterpret_cast<float4*>(out + (size_t)b0 * 72);
            float4* rd4 = reinterpret_cast<float4*>(out + (size_t)B * 72 + (size_t)b0 * 216);
            const int tp = nb * 18, tr = nb * 54;
            #pragma unroll 4
            for (int idx = t; idx < NB * 18; idx += NT) {
                if (idx < tp) {
                    int body = idx / 18;
                    int q    = idx - body * 18;
                    pd4[idx] = cur4[body * 73 + 54 + q];
                }
            }
            #pragma unroll 4
            for (int idx = t; idx < NB * 54; idx += NT) {
                if (idx < tr) {
                    int body = idx / 54;
                    int q    = idx - body * 54;
                    rd4[idx] = cur4[body * 73 + q];
                }
            }
        }
        __syncthreads();   // cur free for the prefetch issued next iteration
        pb ^= 1;
    }
}

extern "C" void kernel_launch(void* const* d_in, const int* in_sizes, int n_in,
                              void* d_out, int out_size)
{
    const float* lr   = (const float*)d_in[0];
    const float* root = (const float*)d_in[1];
    const float* off  = (const float*)d_in[2];

    const int B = in_sizes[0] / (NJ * 9);
    float* out = (float*)d_out;

    cudaFuncSetAttribute(fk_kernel, cudaFuncAttributeMaxDynamicSharedMemorySize,
                         SMEM_BYTES);

    const int numTiles = (B + NB - 1) / NB;
    const int blocks = numTiles < GRID_BLOCKS ? numTiles : GRID_BLOCKS;
    fk_kernel<<<blocks, NT, SMEM_BYTES>>>(lr, root, off, out, B);
}